// round 7
// baseline (speedup 1.0000x reference)
#include <cuda_runtime.h>
#include <cstdint>

#define B 8
#define L 8192
#define C 512
#define NTOK (B * L)           // 65536
#define K_TOP 3687
#define K_RAND 409
#define NBINS 4096
#define SEL_THREADS 1024
#define SMEM_BYTES (32768 + 16384 + 32768 + 8192)   // scores + hist + cand + sel = 90112

// scratch (no allocations allowed)
__device__ float g_norms[NTOK];
__device__ unsigned char g_mask[NTOK];

// ---------------------------------------------------------------------------
// Kernel 1: token L2 norms. 16 threads/token, 8 float4 each (pure read pass,
// measured 23.5us @ 74% DRAM — near practical read ceiling).
// ---------------------------------------------------------------------------
__global__ void norms_kernel(const float4* __restrict__ x) {
    int gt    = blockIdx.x * blockDim.x + threadIdx.x;
    int token = gt >> 4;
    int sub   = gt & 15;
    const float4* p = x + (size_t)token * 128;
    float s = 0.f;
#pragma unroll
    for (int i = 0; i < 8; i++) {
        float4 v = p[sub + i * 16];
        s += v.x * v.x + v.y * v.y + v.z * v.z + v.w * v.w;
    }
#pragma unroll
    for (int o = 8; o; o >>= 1) s += __shfl_xor_sync(0xFFFFFFFFu, s, o, 16);
    if (sub == 0) g_norms[token] = sqrtf(s);
}

// ---------------------------------------------------------------------------
// threefry2x32, JAX-compatible (partitionable, bit_width=32):
// bits[i] = word0 ^ word1 of threefry2x32(key=(0,42), hi=0, lo=i)
// ---------------------------------------------------------------------------
__device__ __forceinline__ uint32_t rotl32(uint32_t x, int d) {
    return (x << d) | (x >> (32 - d));
}

__device__ __forceinline__ uint32_t threefry_xor(uint32_t k1, uint32_t k2,
                                                 uint32_t x0, uint32_t x1) {
    uint32_t ks0 = k1, ks1 = k2, ks2 = k1 ^ k2 ^ 0x1BD11BDAu;
    x0 += ks0; x1 += ks1;
#define TF_R4(a,b,c,d) \
    x0 += x1; x1 = rotl32(x1, a); x1 ^= x0; \
    x0 += x1; x1 = rotl32(x1, b); x1 ^= x0; \
    x0 += x1; x1 = rotl32(x1, c); x1 ^= x0; \
    x0 += x1; x1 = rotl32(x1, d); x1 ^= x0;
    TF_R4(13, 15, 26, 6);  x0 += ks1; x1 += ks2 + 1u;
    TF_R4(17, 29, 16, 24); x0 += ks2; x1 += ks0 + 2u;
    TF_R4(13, 15, 26, 6);  x0 += ks0; x1 += ks1 + 3u;
    TF_R4(17, 29, 16, 24); x0 += ks1; x1 += ks2 + 4u;
    TF_R4(13, 15, 26, 6);  x0 += ks2; x1 += ks0 + 5u;
#undef TF_R4
    return x0 ^ x1;
}

// order-preserving float->uint map
__device__ __forceinline__ unsigned omap(float v) {
    unsigned u = __float_as_uint(v);
    return (u & 0x80000000u) ? ~u : (u | 0x80000000u);
}

// ---------------------------------------------------------------------------
// Exact k-th-largest 64-bit key over 8192 scores within one block.
// key(l) = (omap(score[l]) << 32) | (0xFFFFFFFF - l)  -> distinct keys,
// tie-break = smaller index wins (matches jax.lax.top_k).
// ---------------------------------------------------------------------------
__device__ unsigned long long block_select(const float* sc, unsigned* hist,
                                           unsigned long long* cand, int k, int tid) {
    __shared__ unsigned s_umin, s_umax;
    __shared__ int s_bin, s_need, s_cnt;
    __shared__ unsigned long long s_thr;
    __shared__ unsigned s_wsum[32];
    int lane = tid & 31, wid = tid >> 5;
    if (tid == 0) { s_umin = 0xFFFFFFFFu; s_umax = 0u; s_cnt = 0; }

    unsigned um[8];
    unsigned lmin = 0xFFFFFFFFu, lmax = 0u;
#pragma unroll
    for (int j = 0; j < 8; j++) {
        int l = tid + j * SEL_THREADS;
        unsigned u = omap(sc[l]);
        um[j] = u;
        lmin = min(lmin, u);
        lmax = max(lmax, u);
    }
    reinterpret_cast<uint4*>(hist)[tid] = make_uint4(0u, 0u, 0u, 0u);
    __syncthreads();
    atomicMin(&s_umin, lmin);
    atomicMax(&s_umax, lmax);
    __syncthreads();

    unsigned umin = s_umin;
    unsigned long long span = (unsigned long long)(s_umax - umin) + 1ull;
#pragma unroll
    for (int j = 0; j < 8; j++) {
        unsigned b = (unsigned)(((unsigned long long)(um[j] - umin) * (unsigned long long)NBINS) / span);
        atomicAdd(&hist[b], 1u);
    }
    __syncthreads();

    // suffix counts over the 4 bins this thread owns
    uint4 c = reinterpret_cast<const uint4*>(hist)[tid];
    unsigned s3 = c.w;
    unsigned s2 = c.z + s3;
    unsigned s1 = c.y + s2;
    unsigned s0 = c.x + s1;
    unsigned tot = s0;

    // warp inclusive suffix scan of thread totals
    unsigned inc = tot;
#pragma unroll
    for (int off = 1; off < 32; off <<= 1) {
        unsigned v = __shfl_down_sync(0xFFFFFFFFu, inc, off);
        if (lane < 32 - off) inc += v;
    }
    if (lane == 0) s_wsum[wid] = inc;
    __syncthreads();
    if (wid == 0) {
        unsigned v = s_wsum[lane];
        unsigned inc2 = v;
#pragma unroll
        for (int off = 1; off < 32; off <<= 1) {
            unsigned t = __shfl_down_sync(0xFFFFFFFFu, inc2, off);
            if (lane < 32 - off) inc2 += t;
        }
        s_wsum[lane] = inc2 - v;   // exclusive: count in warps > lane
    }
    __syncthreads();

    unsigned above = s_wsum[wid] + (inc - tot);
    {
        unsigned geq0 = above + s0, abv0 = above + s1;
        unsigned geq1 = above + s1, abv1 = above + s2;
        unsigned geq2 = above + s2, abv2 = above + s3;
        unsigned geq3 = above + s3, abv3 = above;
        unsigned uk = (unsigned)k;
        if (geq0 >= uk && abv0 < uk) { s_bin = 4 * tid + 0; s_need = k - (int)abv0; }
        if (geq1 >= uk && abv1 < uk) { s_bin = 4 * tid + 1; s_need = k - (int)abv1; }
        if (geq2 >= uk && abv2 < uk) { s_bin = 4 * tid + 2; s_need = k - (int)abv2; }
        if (geq3 >= uk && abv3 < uk) { s_bin = 4 * tid + 3; s_need = k - (int)abv3; }
    }
    __syncthreads();

    int bsel = s_bin;
#pragma unroll
    for (int j = 0; j < 8; j++) {
        int l = tid + j * SEL_THREADS;
        unsigned b = (unsigned)(((unsigned long long)(um[j] - umin) * (unsigned long long)NBINS) / span);
        if ((int)b == bsel) {
            int p = atomicAdd(&s_cnt, 1);
            if (p < NBINS)
                cand[p] = ((unsigned long long)um[j] << 32) | (unsigned)(0xFFFFFFFFu - (unsigned)l);
        }
    }
    __syncthreads();

    int cnt  = min(s_cnt, NBINS);
    int need = s_need;
    for (int i = tid; i < cnt; i += SEL_THREADS) {
        unsigned long long ki = cand[i];
        int r = 0;
        for (int j = 0; j < cnt; j++) r += (cand[j] > ki);
        if (r == need - 1) s_thr = ki;
    }
    __syncthreads();
    return s_thr;
}

// ---------------------------------------------------------------------------
// Kernel 2: per-row selection (block = batch row). Threefry computed here.
// ---------------------------------------------------------------------------
__global__ void select_kernel() {
    extern __shared__ unsigned char smraw[];
    float*              s_score = (float*)smraw;                          // 32768 B
    unsigned*           s_hist  = (unsigned*)(smraw + 32768);             // 16384 B
    unsigned long long* s_cand  = (unsigned long long*)(smraw + 49152);   // 32768 B
    unsigned char*      s_sel   = (unsigned char*)(smraw + 81920);        //  8192 B

    int row = blockIdx.x;
    int tid = threadIdx.x;
    const float* norms = &g_norms[row * L];

#pragma unroll
    for (int j = 0; j < 8; j++) {
        int l = tid + j * SEL_THREADS;
        s_score[l] = norms[l];
    }
    __syncthreads();

    unsigned long long thr = block_select(s_score, s_hist, s_cand, K_TOP, tid);
#pragma unroll
    for (int j = 0; j < 8; j++) {
        int l = tid + j * SEL_THREADS;
        unsigned long long key =
            ((unsigned long long)omap(s_score[l]) << 32) | (unsigned)(0xFFFFFFFFu - (unsigned)l);
        s_sel[l] = (key >= thr) ? 1 : 0;
    }
    __syncthreads();

#pragma unroll
    for (int j = 0; j < 8; j++) {
        int l = tid + j * SEL_THREADS;
        unsigned i = (unsigned)(row * L + l);
        unsigned bits = threefry_xor(0u, 42u, 0u, i);
        float r = __uint_as_float((bits >> 9) | 0x3F800000u) - 1.0f;
        s_score[l] = s_sel[l] ? -1.0f : r;
    }
    __syncthreads();

    thr = block_select(s_score, s_hist, s_cand, K_RAND, tid);
#pragma unroll
    for (int j = 0; j < 8; j++) {
        int l = tid + j * SEL_THREADS;
        unsigned long long key =
            ((unsigned long long)omap(s_score[l]) << 32) | (unsigned)(0xFFFFFFFFu - (unsigned)l);
        g_mask[row * L + l] = s_sel[l] | ((key >= thr) ? 1 : 0);
    }
}

// ---------------------------------------------------------------------------
// Kernel 3: dense branchless masking pass: out[i] = mask[token] ? x[i] : 0.
// Reads ALL of x (dense stream, no holes -> full DRAM page streaming
// efficiency; R6 measured 7.0 TB/s aggregate for this access shape).
// 4 float4 per thread, predicated select, no divergence.
// ---------------------------------------------------------------------------
__global__ void mask_mul_kernel(const float4* __restrict__ x,
                                float4* __restrict__ out) {
    int base = blockIdx.x * 1024 + threadIdx.x;      // 8 tokens per block
    float4 z = make_float4(0.f, 0.f, 0.f, 0.f);
    int idx[4];
    unsigned m[4];
    float4 v[4];
#pragma unroll
    for (int k = 0; k < 4; k++) {
        idx[k] = base + k * 256;
        m[k]   = g_mask[idx[k] >> 7];
        v[k]   = x[idx[k]];                          // unconditional load
    }
#pragma unroll
    for (int k = 0; k < 4; k++) {
        out[idx[k]] = m[k] ? v[k] : z;
    }
}

extern "C" void kernel_launch(void* const* d_in, const int* in_sizes, int n_in,
                              void* d_out, int out_size) {
    (void)in_sizes; (void)n_in; (void)out_size;
    const float4* x   = (const float4*)d_in[0];
    float4*       out = (float4*)d_out;

    cudaFuncSetAttribute(select_kernel,
                         cudaFuncAttributeMaxDynamicSharedMemorySize, SMEM_BYTES);

    norms_kernel<<<NTOK * 16 / 256, 256>>>(x);
    select_kernel<<<B, SEL_THREADS, SMEM_BYTES>>>();
    mask_mul_kernel<<<NTOK * 128 / 1024, 256>>>(x, out);
}

// round 8
// speedup vs baseline: 1.3480x; 1.3480x over previous
#include <cuda_runtime.h>
#include <cstdint>

#define B 8
#define L 8192
#define C 512
#define NTOK (B * L)           // 65536
#define K_TOP 3687
#define K_RAND 409
#define N_DROP_ROW 4096        // L - keep_len, exact
#define NBINS 4096
#define SEL_THREADS 1024
#define SMEM_BYTES (32768 + 16384 + 32768 + 8192)   // scores + hist + cand + sel = 90112

// scratch (no allocations allowed)
__device__ float g_norms[NTOK];
__device__ int   g_dropped[NTOK / 2];   // 32768 dropped token ids (global)

// ---------------------------------------------------------------------------
// Kernel 1: token L2 norms + full copy x -> out (measured 36.6us, 7.0 TB/s).
// 16 threads/token, 8 float4 per thread; copy reuses the norm loads' registers.
// This is the ONLY kernel that reads x.
// ---------------------------------------------------------------------------
__global__ void norms_copy_kernel(const float4* __restrict__ x,
                                  float4* __restrict__ out) {
    int gt    = blockIdx.x * blockDim.x + threadIdx.x;
    int token = gt >> 4;
    int sub   = gt & 15;
    size_t base = (size_t)token * 128;
    float s = 0.f;
#pragma unroll
    for (int i = 0; i < 8; i++) {
        float4 v = x[base + sub + i * 16];
        out[base + sub + i * 16] = v;
        s += v.x * v.x + v.y * v.y + v.z * v.z + v.w * v.w;
    }
#pragma unroll
    for (int o = 8; o; o >>= 1) s += __shfl_xor_sync(0xFFFFFFFFu, s, o, 16);
    if (sub == 0) g_norms[token] = sqrtf(s);
}

// ---------------------------------------------------------------------------
// threefry2x32, JAX-compatible (partitionable, bit_width=32):
// bits[i] = word0 ^ word1 of threefry2x32(key=(0,42), hi=0, lo=i)
// ---------------------------------------------------------------------------
__device__ __forceinline__ uint32_t rotl32(uint32_t x, int d) {
    return (x << d) | (x >> (32 - d));
}

__device__ __forceinline__ uint32_t threefry_xor(uint32_t k1, uint32_t k2,
                                                 uint32_t x0, uint32_t x1) {
    uint32_t ks0 = k1, ks1 = k2, ks2 = k1 ^ k2 ^ 0x1BD11BDAu;
    x0 += ks0; x1 += ks1;
#define TF_R4(a,b,c,d) \
    x0 += x1; x1 = rotl32(x1, a); x1 ^= x0; \
    x0 += x1; x1 = rotl32(x1, b); x1 ^= x0; \
    x0 += x1; x1 = rotl32(x1, c); x1 ^= x0; \
    x0 += x1; x1 = rotl32(x1, d); x1 ^= x0;
    TF_R4(13, 15, 26, 6);  x0 += ks1; x1 += ks2 + 1u;
    TF_R4(17, 29, 16, 24); x0 += ks2; x1 += ks0 + 2u;
    TF_R4(13, 15, 26, 6);  x0 += ks0; x1 += ks1 + 3u;
    TF_R4(17, 29, 16, 24); x0 += ks1; x1 += ks2 + 4u;
    TF_R4(13, 15, 26, 6);  x0 += ks2; x1 += ks0 + 5u;
#undef TF_R4
    return x0 ^ x1;
}

// order-preserving float->uint map
__device__ __forceinline__ unsigned omap(float v) {
    unsigned u = __float_as_uint(v);
    return (u & 0x80000000u) ? ~u : (u | 0x80000000u);
}

// ---------------------------------------------------------------------------
// Exact k-th-largest 64-bit key over 8192 scores within one block.
// key(l) = (omap(score[l]) << 32) | (0xFFFFFFFF - l)  -> distinct keys,
// tie-break = smaller index wins (matches jax.lax.top_k).
// ---------------------------------------------------------------------------
__device__ unsigned long long block_select(const float* sc, unsigned* hist,
                                           unsigned long long* cand, int k, int tid) {
    __shared__ unsigned s_umin, s_umax;
    __shared__ int s_bin, s_need, s_cnt;
    __shared__ unsigned long long s_thr;
    __shared__ unsigned s_wsum[32];
    int lane = tid & 31, wid = tid >> 5;
    if (tid == 0) { s_umin = 0xFFFFFFFFu; s_umax = 0u; s_cnt = 0; }

    unsigned um[8];
    unsigned lmin = 0xFFFFFFFFu, lmax = 0u;
#pragma unroll
    for (int j = 0; j < 8; j++) {
        int l = tid + j * SEL_THREADS;
        unsigned u = omap(sc[l]);
        um[j] = u;
        lmin = min(lmin, u);
        lmax = max(lmax, u);
    }
    reinterpret_cast<uint4*>(hist)[tid] = make_uint4(0u, 0u, 0u, 0u);
    __syncthreads();
    atomicMin(&s_umin, lmin);
    atomicMax(&s_umax, lmax);
    __syncthreads();

    unsigned umin = s_umin;
    unsigned long long span = (unsigned long long)(s_umax - umin) + 1ull;
#pragma unroll
    for (int j = 0; j < 8; j++) {
        unsigned b = (unsigned)(((unsigned long long)(um[j] - umin) * (unsigned long long)NBINS) / span);
        atomicAdd(&hist[b], 1u);
    }
    __syncthreads();

    // suffix counts over the 4 bins this thread owns
    uint4 c = reinterpret_cast<const uint4*>(hist)[tid];
    unsigned s3 = c.w;
    unsigned s2 = c.z + s3;
    unsigned s1 = c.y + s2;
    unsigned s0 = c.x + s1;
    unsigned tot = s0;

    // warp inclusive suffix scan of thread totals
    unsigned inc = tot;
#pragma unroll
    for (int off = 1; off < 32; off <<= 1) {
        unsigned v = __shfl_down_sync(0xFFFFFFFFu, inc, off);
        if (lane < 32 - off) inc += v;
    }
    if (lane == 0) s_wsum[wid] = inc;
    __syncthreads();
    if (wid == 0) {
        unsigned v = s_wsum[lane];
        unsigned inc2 = v;
#pragma unroll
        for (int off = 1; off < 32; off <<= 1) {
            unsigned t = __shfl_down_sync(0xFFFFFFFFu, inc2, off);
            if (lane < 32 - off) inc2 += t;
        }
        s_wsum[lane] = inc2 - v;   // exclusive: count in warps > lane
    }
    __syncthreads();

    unsigned above = s_wsum[wid] + (inc - tot);
    {
        unsigned geq0 = above + s0, abv0 = above + s1;
        unsigned geq1 = above + s1, abv1 = above + s2;
        unsigned geq2 = above + s2, abv2 = above + s3;
        unsigned geq3 = above + s3, abv3 = above;
        unsigned uk = (unsigned)k;
        if (geq0 >= uk && abv0 < uk) { s_bin = 4 * tid + 0; s_need = k - (int)abv0; }
        if (geq1 >= uk && abv1 < uk) { s_bin = 4 * tid + 1; s_need = k - (int)abv1; }
        if (geq2 >= uk && abv2 < uk) { s_bin = 4 * tid + 2; s_need = k - (int)abv2; }
        if (geq3 >= uk && abv3 < uk) { s_bin = 4 * tid + 3; s_need = k - (int)abv3; }
    }
    __syncthreads();

    int bsel = s_bin;
#pragma unroll
    for (int j = 0; j < 8; j++) {
        int l = tid + j * SEL_THREADS;
        unsigned b = (unsigned)(((unsigned long long)(um[j] - umin) * (unsigned long long)NBINS) / span);
        if ((int)b == bsel) {
            int p = atomicAdd(&s_cnt, 1);
            if (p < NBINS)
                cand[p] = ((unsigned long long)um[j] << 32) | (unsigned)(0xFFFFFFFFu - (unsigned)l);
        }
    }
    __syncthreads();

    int cnt  = min(s_cnt, NBINS);
    int need = s_need;
    for (int i = tid; i < cnt; i += SEL_THREADS) {
        unsigned long long ki = cand[i];
        int r = 0;
        for (int j = 0; j < cnt; j++) r += (cand[j] > ki);
        if (r == need - 1) s_thr = ki;
    }
    __syncthreads();
    return s_thr;
}

// ---------------------------------------------------------------------------
// Kernel 2: per-row selection (block = batch row). Emits the compact list of
// DROPPED token ids (exactly 4096 per row) instead of a mask.
// ---------------------------------------------------------------------------
__global__ void select_kernel() {
    extern __shared__ unsigned char smraw[];
    float*              s_score = (float*)smraw;                          // 32768 B
    unsigned*           s_hist  = (unsigned*)(smraw + 32768);             // 16384 B
    unsigned long long* s_cand  = (unsigned long long*)(smraw + 49152);   // 32768 B
    unsigned char*      s_sel   = (unsigned char*)(smraw + 81920);        //  8192 B
    __shared__ int s_dcnt;

    int row = blockIdx.x;
    int tid = threadIdx.x;
    const float* norms = &g_norms[row * L];
    if (tid == 0) s_dcnt = 0;

#pragma unroll
    for (int j = 0; j < 8; j++) {
        int l = tid + j * SEL_THREADS;
        s_score[l] = norms[l];
    }
    __syncthreads();

    unsigned long long thr = block_select(s_score, s_hist, s_cand, K_TOP, tid);
#pragma unroll
    for (int j = 0; j < 8; j++) {
        int l = tid + j * SEL_THREADS;
        unsigned long long key =
            ((unsigned long long)omap(s_score[l]) << 32) | (unsigned)(0xFFFFFFFFu - (unsigned)l);
        s_sel[l] = (key >= thr) ? 1 : 0;
    }
    __syncthreads();

#pragma unroll
    for (int j = 0; j < 8; j++) {
        int l = tid + j * SEL_THREADS;
        unsigned i = (unsigned)(row * L + l);
        unsigned bits = threefry_xor(0u, 42u, 0u, i);
        float r = __uint_as_float((bits >> 9) | 0x3F800000u) - 1.0f;
        s_score[l] = s_sel[l] ? -1.0f : r;
    }
    __syncthreads();

    thr = block_select(s_score, s_hist, s_cand, K_RAND, tid);
#pragma unroll
    for (int j = 0; j < 8; j++) {
        int l = tid + j * SEL_THREADS;
        unsigned long long key =
            ((unsigned long long)omap(s_score[l]) << 32) | (unsigned)(0xFFFFFFFFu - (unsigned)l);
        int kept = s_sel[l] | ((key >= thr) ? 1 : 0);
        if (!kept) {
            int p = atomicAdd(&s_dcnt, 1);
            g_dropped[row * N_DROP_ROW + p] = row * L + l;   // global token id
        }
    }
}

// ---------------------------------------------------------------------------
// Kernel 3: zero the dropped tokens via the compact list. 1 warp per token,
// 4 float4 stores per thread (2KB contiguous per warp). Pure writes, no reads
// of x, every warp does real work. 64MB total.
// ---------------------------------------------------------------------------
__global__ void zero_list_kernel(float4* __restrict__ out) {
    int d     = blockIdx.x * 8 + (threadIdx.x >> 5);   // dropped-list index
    int lane  = threadIdx.x & 31;
    int token = g_dropped[d];
    size_t base = (size_t)token * 128;
    float4 z = make_float4(0.f, 0.f, 0.f, 0.f);
#pragma unroll
    for (int i = 0; i < 4; i++) out[base + lane + i * 32] = z;
}

extern "C" void kernel_launch(void* const* d_in, const int* in_sizes, int n_in,
                              void* d_out, int out_size) {
    (void)in_sizes; (void)n_in; (void)out_size;
    const float4* x   = (const float4*)d_in[0];
    float4*       out = (float4*)d_out;

    cudaFuncSetAttribute(select_kernel,
                         cudaFuncAttributeMaxDynamicSharedMemorySize, SMEM_BYTES);

    norms_copy_kernel<<<NTOK * 16 / 256, 256>>>(x, out);
    select_kernel<<<B, SEL_THREADS, SMEM_BYTES>>>();
    zero_list_kernel<<<(NTOK / 2) / 8, 256>>>(out);
}

// round 9
// speedup vs baseline: 1.6194x; 1.2014x over previous
#include <cuda_runtime.h>
#include <cstdint>

#define B 8
#define L 8192
#define C 512
#define NTOK (B * L)           // 65536
#define K_TOP 3687
#define K_RAND 409
#define N_DROP_ROW 4096        // L - keep_len, exact
#define NBINS 4096
#define SEL_THREADS 1024
// dyn smem: hist 16384 + cand 65536 + sel 8192 = 90112
#define SMEM_BYTES (16384 + 65536 + 8192)

// scratch (no allocations allowed)
__device__ float g_norms[NTOK];
__device__ int   g_dropped[NTOK / 2];   // 32768 dropped token ids (global)

// ---------------------------------------------------------------------------
// Kernel 1: token L2 norms + full copy x -> out (measured 37us, ~7 TB/s).
// The ONLY kernel that reads x.
// ---------------------------------------------------------------------------
__global__ void norms_copy_kernel(const float4* __restrict__ x,
                                  float4* __restrict__ out) {
    int gt    = blockIdx.x * blockDim.x + threadIdx.x;
    int token = gt >> 4;
    int sub   = gt & 15;
    size_t base = (size_t)token * 128;
    float s = 0.f;
#pragma unroll
    for (int i = 0; i < 8; i++) {
        float4 v = x[base + sub + i * 16];
        out[base + sub + i * 16] = v;
        s += v.x * v.x + v.y * v.y + v.z * v.z + v.w * v.w;
    }
#pragma unroll
    for (int o = 8; o; o >>= 1) s += __shfl_xor_sync(0xFFFFFFFFu, s, o, 16);
    if (sub == 0) g_norms[token] = sqrtf(s);
}

// ---------------------------------------------------------------------------
// threefry2x32, JAX-compatible (partitionable, bit_width=32):
// bits[i] = word0 ^ word1 of threefry2x32(key=(0,42), hi=0, lo=i)
// ---------------------------------------------------------------------------
__device__ __forceinline__ uint32_t rotl32(uint32_t x, int d) {
    return (x << d) | (x >> (32 - d));
}

__device__ __forceinline__ uint32_t threefry_xor(uint32_t k1, uint32_t k2,
                                                 uint32_t x0, uint32_t x1) {
    uint32_t ks0 = k1, ks1 = k2, ks2 = k1 ^ k2 ^ 0x1BD11BDAu;
    x0 += ks0; x1 += ks1;
#define TF_R4(a,b,c,d) \
    x0 += x1; x1 = rotl32(x1, a); x1 ^= x0; \
    x0 += x1; x1 = rotl32(x1, b); x1 ^= x0; \
    x0 += x1; x1 = rotl32(x1, c); x1 ^= x0; \
    x0 += x1; x1 = rotl32(x1, d); x1 ^= x0;
    TF_R4(13, 15, 26, 6);  x0 += ks1; x1 += ks2 + 1u;
    TF_R4(17, 29, 16, 24); x0 += ks2; x1 += ks0 + 2u;
    TF_R4(13, 15, 26, 6);  x0 += ks0; x1 += ks1 + 3u;
    TF_R4(17, 29, 16, 24); x0 += ks1; x1 += ks2 + 4u;
    TF_R4(13, 15, 26, 6);  x0 += ks2; x1 += ks0 + 5u;
#undef TF_R4
    return x0 ^ x1;
}

// order-preserving float->uint map (all norms are >= 0 but keep general form)
__device__ __forceinline__ unsigned omap(float v) {
    unsigned u = __float_as_uint(v);
    return (u & 0x80000000u) ? ~u : (u | 0x80000000u);
}

// ---------------------------------------------------------------------------
// Exact k-th-largest 64-bit key among the 8192 keys
// key(l) = ((u64)um[l] << 32) | (0xFFFFFFFF - l)   (distinct; smaller index
// wins ties — matches jax.lax.top_k).
// Binning: bin = (um - umin) >> shift  (monotone, no division).
// Exactness comes from the rank-select over full 64-bit keys in the boundary
// bin; binning only needs to be monotone + deterministic.
// ---------------------------------------------------------------------------
__device__ unsigned long long block_select(const unsigned um[8],
                                           unsigned umin, int shift,
                                           unsigned* hist, unsigned long long* cand,
                                           int k, int tid) {
    __shared__ int s_bin, s_need, s_cnt;
    __shared__ unsigned long long s_thr;
    __shared__ unsigned s_wsum[32];
    int lane = tid & 31, wid = tid >> 5;

    if (tid == 0) s_cnt = 0;
    reinterpret_cast<uint4*>(hist)[tid] = make_uint4(0u, 0u, 0u, 0u);
    __syncthreads();

#pragma unroll
    for (int j = 0; j < 8; j++)
        atomicAdd(&hist[(um[j] - umin) >> shift], 1u);
    __syncthreads();

    // suffix counts over the 4 bins this thread owns
    uint4 c = reinterpret_cast<const uint4*>(hist)[tid];
    unsigned s3 = c.w;
    unsigned s2 = c.z + s3;
    unsigned s1 = c.y + s2;
    unsigned s0 = c.x + s1;
    unsigned tot = s0;

    // warp inclusive suffix scan of thread totals
    unsigned inc = tot;
#pragma unroll
    for (int off = 1; off < 32; off <<= 1) {
        unsigned v = __shfl_down_sync(0xFFFFFFFFu, inc, off);
        if (lane < 32 - off) inc += v;
    }
    if (lane == 0) s_wsum[wid] = inc;
    __syncthreads();
    if (wid == 0) {
        unsigned v = s_wsum[lane];
        unsigned inc2 = v;
#pragma unroll
        for (int off = 1; off < 32; off <<= 1) {
            unsigned t = __shfl_down_sync(0xFFFFFFFFu, inc2, off);
            if (lane < 32 - off) inc2 += t;
        }
        s_wsum[lane] = inc2 - v;   // exclusive: count in warps > lane
    }
    __syncthreads();

    unsigned above = s_wsum[wid] + (inc - tot);
    {
        unsigned geq0 = above + s0, abv0 = above + s1;
        unsigned geq1 = above + s1, abv1 = above + s2;
        unsigned geq2 = above + s2, abv2 = above + s3;
        unsigned geq3 = above + s3, abv3 = above;
        unsigned uk = (unsigned)k;
        if (geq0 >= uk && abv0 < uk) { s_bin = 4 * tid + 0; s_need = k - (int)abv0; }
        if (geq1 >= uk && abv1 < uk) { s_bin = 4 * tid + 1; s_need = k - (int)abv1; }
        if (geq2 >= uk && abv2 < uk) { s_bin = 4 * tid + 2; s_need = k - (int)abv2; }
        if (geq3 >= uk && abv3 < uk) { s_bin = 4 * tid + 3; s_need = k - (int)abv3; }
    }
    __syncthreads();

    int bsel = s_bin;
#pragma unroll
    for (int j = 0; j < 8; j++) {
        if ((int)((um[j] - umin) >> shift) == bsel) {
            int p = atomicAdd(&s_cnt, 1);
            int l = tid + j * SEL_THREADS;
            cand[p] = ((unsigned long long)um[j] << 32) | (unsigned)(0xFFFFFFFFu - (unsigned)l);
        }
    }
    __syncthreads();

    int cnt  = s_cnt;          // cand sized 8192: can never overflow
    int need = s_need;
    for (int i = tid; i < cnt; i += SEL_THREADS) {
        unsigned long long ki = cand[i];
        int r = 0;
        for (int j = 0; j < cnt; j++) r += (cand[j] > ki);
        if (r == need - 1) s_thr = ki;
    }
    __syncthreads();
    return s_thr;
}

// ---------------------------------------------------------------------------
// Kernel 2: per-row selection (block = batch row). Emits compact dropped list.
// Pass 1: top-K_TOP of norms (omap keys, min/max + shift binning).
// Pass 2: top-K_RAND of threefry uniforms among the rest. Uniform value is a
// strictly-monotone exact function of (bits>>9), so the raw 23-bit ints ARE
// the sort keys (masked -> 0 sentinel; threshold sits at ~0.91, so sentinel
// can never be selected). bin = key >> 11: perfectly uniform histogram.
// ---------------------------------------------------------------------------
__global__ void select_kernel() {
    extern __shared__ unsigned char smraw[];
    unsigned*           s_hist = (unsigned*)smraw;                        // 16384 B
    unsigned long long* s_cand = (unsigned long long*)(smraw + 16384);    // 65536 B
    unsigned char*      s_sel  = (unsigned char*)(smraw + 81920);         //  8192 B
    __shared__ unsigned s_minw[32], s_maxw[32];
    __shared__ unsigned s_umin, s_span;
    __shared__ int s_dcnt;

    int row = blockIdx.x;
    int tid = threadIdx.x;
    int lane = tid & 31, wid = tid >> 5;
    const float* norms = &g_norms[row * L];
    if (tid == 0) s_dcnt = 0;

    // ---- pass 1: keys = omap(norm) ----
    unsigned um[8];
    unsigned lmin = 0xFFFFFFFFu, lmax = 0u;
#pragma unroll
    for (int j = 0; j < 8; j++) {
        unsigned u = omap(norms[tid + j * SEL_THREADS]);
        um[j] = u;
        lmin = min(lmin, u);
        lmax = max(lmax, u);
    }
#pragma unroll
    for (int o = 16; o; o >>= 1) {
        lmin = min(lmin, __shfl_xor_sync(0xFFFFFFFFu, lmin, o));
        lmax = max(lmax, __shfl_xor_sync(0xFFFFFFFFu, lmax, o));
    }
    if (lane == 0) { s_minw[wid] = lmin; s_maxw[wid] = lmax; }
    __syncthreads();
    if (wid == 0) {
        unsigned m = s_minw[lane], M = s_maxw[lane];
#pragma unroll
        for (int o = 16; o; o >>= 1) {
            m = min(m, __shfl_xor_sync(0xFFFFFFFFu, m, o));
            M = max(M, __shfl_xor_sync(0xFFFFFFFFu, M, o));
        }
        if (lane == 0) { s_umin = m; s_span = M - m; }
    }
    __syncthreads();
    unsigned umin = s_umin;
    int shift = 20 - __clz(s_span | 1);
    if (shift < 0) shift = 0;

    unsigned long long thr = block_select(um, umin, shift, s_hist, s_cand, K_TOP, tid);
#pragma unroll
    for (int j = 0; j < 8; j++) {
        int l = tid + j * SEL_THREADS;
        unsigned long long key =
            ((unsigned long long)um[j] << 32) | (unsigned)(0xFFFFFFFFu - (unsigned)l);
        s_sel[l] = (key >= thr) ? 1 : 0;
    }
    __syncthreads();

    // ---- pass 2: keys = bits>>9 (23-bit), masked -> 0 ----
#pragma unroll
    for (int j = 0; j < 8; j++) {
        int l = tid + j * SEL_THREADS;
        unsigned bits = threefry_xor(0u, 42u, 0u, (unsigned)(row * L + l));
        um[j] = s_sel[l] ? 0u : (bits >> 9);
    }
    __syncthreads();   // s_sel reads done before pass 2 reuses smem? (hist/cand only) — keep for safety

    thr = block_select(um, 0u, 11, s_hist, s_cand, K_RAND, tid);
#pragma unroll
    for (int j = 0; j < 8; j++) {
        int l = tid + j * SEL_THREADS;
        unsigned long long key =
            ((unsigned long long)um[j] << 32) | (unsigned)(0xFFFFFFFFu - (unsigned)l);
        int kept = s_sel[l] | ((key >= thr) ? 1 : 0);
        if (!kept) {
            int p = atomicAdd(&s_dcnt, 1);
            g_dropped[row * N_DROP_ROW + p] = row * L + l;
        }
    }
}

// ---------------------------------------------------------------------------
// Kernel 3: zero dropped tokens via the compact list. 2 tokens per 256-thread
// block, 1 float4 store per thread. Pure writes, full-chip parallelism.
// ---------------------------------------------------------------------------
__global__ void zero_list_kernel(float4* __restrict__ out) {
    int d     = blockIdx.x * 2 + (threadIdx.x >> 7);
    int j     = threadIdx.x & 127;
    int token = g_dropped[d];
    out[(size_t)token * 128 + j] = make_float4(0.f, 0.f, 0.f, 0.f);
}

extern "C" void kernel_launch(void* const* d_in, const int* in_sizes, int n_in,
                              void* d_out, int out_size) {
    (void)in_sizes; (void)n_in; (void)out_size;
    const float4* x   = (const float4*)d_in[0];
    float4*       out = (float4*)d_out;

    cudaFuncSetAttribute(select_kernel,
                         cudaFuncAttributeMaxDynamicSharedMemorySize, SMEM_BYTES);

    norms_copy_kernel<<<NTOK * 16 / 256, 256>>>(x, out);
    select_kernel<<<B, SEL_THREADS, SMEM_BYTES>>>();
    zero_list_kernel<<<(NTOK / 2) / 2, 256>>>(out);
}